// round 9
// baseline (speedup 1.0000x reference)
#include <cuda_runtime.h>

// PairwisePotential1 on sm_103a — warp-per-2-rows, shuffle halo.
// MUFU-roofline buster: 5 of 64 exp terms per thread computed via FMA-pipe
// polynomial exp2 (magic-constant range reduction + deg-4 poly), rest on MUFU.
// out[b,c,h,w] = w1[c,hw]*(first/9) + w2[c,hw]*((4+4*sqrt2)/9)
// first = 1 + sum_{(i,j) in {0,1,2}^2\{0,0}} exp(-0.5*(xp[h][w]-xp[h+i][w+j])^2 - 0.5*d)

constexpr int S = 128;
constexpr int C = 64;

#define KH    (-0.72134752044448170368f)   // -0.5*log2(e)
#define CD1   (-0.72134752044448170368f)   // -0.5*1*log2(e)
#define CD2   (-1.02013364214765880189f)   // -0.5*sqrt(2)*log2(e)
#define SEC9  (1.07298380546472528f)       // (4+4*sqrt2)/9
#define NINTH (0.11111111111111111111f)
#define MAGIC (12582912.0f)                // 1.5 * 2^23

__device__ __forceinline__ float ex2a(float a) {
    float r; asm("ex2.approx.ftz.f32 %0, %1;" : "=f"(r) : "f"(a)); return r;
}

// MUFU term
__device__ __forceinline__ float term(float c, float n, float cd) {
    float u = c - n;
    float t = u * u;
    return ex2a(fmaf(t, KH, cd));
}

// FMA-pipe term: exp2(arg) with arg in [-105, 0]. Magic-add rounds arg to
// nearest int k (f in [-0.5, 0.5]); 2^k built in the exponent field (ALU pipe);
// deg-4 poly for 2^f (rel err ~3e-5). Returns the term value.
__device__ __forceinline__ float pterm(float c, float n, float cd) {
    float u   = c - n;
    float t   = u * u;
    float arg = fmaf(t, KH, cd);
    float y   = arg + MAGIC;
    float f   = arg - (y - MAGIC);
    int   sb  = (__float_as_int(y) + (127 - 0x4B400000)) << 23;   // 2^k bits
    float p   = fmaf(f, 0.0096181291f, 0.0555041087f);
    p = fmaf(f, p, 0.2402265069f);
    p = fmaf(f, p, 0.6931471806f);
    p = fmaf(f, p, 1.0f);
    return p * __int_as_float(sb);
}

__global__ __launch_bounds__(256)
void pairwise_kernel(const float* __restrict__ x,
                     const float* __restrict__ w1,
                     const float* __restrict__ w2,
                     float* __restrict__ out) {
    const int b  = blockIdx.x;             // batch fastest -> w1/w2 L2 reuse
    const int ty = blockIdx.y;             // 0..7 (16 rows per CTA)
    const int c  = blockIdx.z;
    const int t  = threadIdx.x & 31;
    const int wd = threadIdx.x >> 5;
    const int h  = ty * 16 + wd * 2;       // first output row
    const int w4 = t * 4;

    const size_t plane = (size_t)(b * C + c) * (S * S);
    const int    pix0  = h * S + w4;

    const float* w1p = w1 + (size_t)c * (S * S) + pix0;
    const float* w2p = w2 + (size_t)c * (S * S) + pix0;
    const float4 W1a = *(const float4*)(w1p);
    const float4 W1b = *(const float4*)(w1p + S);
    const float4 W2a = *(const float4*)(w2p);
    const float4 W2b = *(const float4*)(w2p + S);

    // Four x rows: unpadded h-1 .. h+2 (warp-uniform bounds).
    const float* xr = x + plane + (h - 1) * S + w4;
    float4 v0 = make_float4(0.f, 0.f, 0.f, 0.f);
    float4 v3 = make_float4(0.f, 0.f, 0.f, 0.f);
    if (h >= 1)      v0 = *(const float4*)(xr);
    float4 v1 = *(const float4*)(xr + S);
    float4 v2 = *(const float4*)(xr + 2 * S);
    if (h + 2 < S)   v3 = *(const float4*)(xr + 3 * S);

    // Halo via shuffle.
    float L0 = __shfl_up_sync(0xffffffffu, v0.w, 1);
    float L1 = __shfl_up_sync(0xffffffffu, v1.w, 1);
    float L2 = __shfl_up_sync(0xffffffffu, v2.w, 1);
    float L3 = __shfl_up_sync(0xffffffffu, v3.w, 1);
    float R0 = __shfl_down_sync(0xffffffffu, v0.x, 1);
    float R1 = __shfl_down_sync(0xffffffffu, v1.x, 1);
    float R2 = __shfl_down_sync(0xffffffffu, v2.x, 1);
    float R3 = __shfl_down_sync(0xffffffffu, v3.x, 1);
    if (t == 0)  { L0 = 0.f; L1 = 0.f; L2 = 0.f; L3 = 0.f; }
    if (t == 31) { R0 = 0.f; R1 = 0.f; R2 = 0.f; R3 = 0.f; }

    const float s0[6] = {L0, v0.x, v0.y, v0.z, v0.w, R0};
    const float s1[6] = {L1, v1.x, v1.y, v1.z, v1.w, R1};
    const float s2[6] = {L2, v2.x, v2.y, v2.z, v2.w, R2};
    const float s3[6] = {L3, v3.x, v3.y, v3.z, v3.w, R3};

    float fA[4], fB[4];
    #pragma unroll
    for (int k = 0; k < 4; k++) {
        // --- output row h: center s0[k] ---
        {
            const float cv = s0[k];
            float a0, a1;
            a0  = term (cv, s0[k + 1], CD1);
            a1  = term (cv, s0[k + 2], CD1);
            a0 += term (cv, s1[k],     CD1);
            a1 += pterm(cv, s1[k + 1], CD2);   // (1,1) on FMA pipe (all 4 k)
            a0 += term (cv, s1[k + 2], CD2);
            a1 += term (cv, s2[k],     CD1);
            a0 += term (cv, s2[k + 1], CD2);
            a1 += term (cv, s2[k + 2], CD2);
            fA[k] = a0 + a1;
        }
        // --- output row h+1: center s1[k] ---
        {
            const float cv = s1[k];
            float a0, a1;
            a0  = term (cv, s1[k + 1], CD1);
            a1  = term (cv, s1[k + 2], CD1);
            a0 += term (cv, s2[k],     CD1);
            if (k == 0) a1 += pterm(cv, s2[k + 1], CD2);  // 5th poly term
            else        a1 += term (cv, s2[k + 1], CD2);
            a0 += term (cv, s2[k + 2], CD2);
            a1 += term (cv, s3[k],     CD1);
            a0 += term (cv, s3[k + 1], CD2);
            a1 += term (cv, s3[k + 2], CD2);
            fB[k] = a0 + a1;
        }
    }

    float4 oa, ob;
    oa.x = fmaf(W1a.x, fmaf(fA[0], NINTH, NINTH), W2a.x * SEC9);
    oa.y = fmaf(W1a.y, fmaf(fA[1], NINTH, NINTH), W2a.y * SEC9);
    oa.z = fmaf(W1a.z, fmaf(fA[2], NINTH, NINTH), W2a.z * SEC9);
    oa.w = fmaf(W1a.w, fmaf(fA[3], NINTH, NINTH), W2a.w * SEC9);
    ob.x = fmaf(W1b.x, fmaf(fB[0], NINTH, NINTH), W2b.x * SEC9);
    ob.y = fmaf(W1b.y, fmaf(fB[1], NINTH, NINTH), W2b.y * SEC9);
    ob.z = fmaf(W1b.z, fmaf(fB[2], NINTH, NINTH), W2b.z * SEC9);
    ob.w = fmaf(W1b.w, fmaf(fB[3], NINTH, NINTH), W2b.w * SEC9);
    float* op = out + plane + pix0;
    *(float4*)(op)     = oa;
    *(float4*)(op + S) = ob;
}

extern "C" void kernel_launch(void* const* d_in, const int* in_sizes, int n_in,
                              void* d_out, int out_size) {
    const float* x  = (const float*)d_in[0];
    const float* w1 = (const float*)d_in[1];
    const float* w2 = (const float*)d_in[2];
    float* out = (float*)d_out;

    int B = in_sizes[0] / (C * S * S);     // 16
    dim3 grid(B, S / 16, C);
    pairwise_kernel<<<grid, 256>>>(x, w1, w2, out);
}